// round 2
// baseline (speedup 1.0000x reference)
#include <cuda_runtime.h>
#include <cuda_bf16.h>

// ---------------------------------------------------------------------------
// BoxMultiHeadedAttention  (B=16, N=256, D=512, H=8, d_k=64, dim_g=64)
//
// Pipeline:
//  K1 qkv_kernel     : q,k,v = (X @ W + b) permuted to [B,H,N,64]
//  K2 geo_bias_kernel: bias[b,h,n,m] = log(max(relu(geo·Wg+bg),1e-6)) (+mask)
//  K3 scores_kernel  : bias += (q·k^T)/8     (in place -> logits)
//  K4 softmax_kernel : softmax over last dim (in place -> probs)
//  K5 pv_kernel      : attn[b,n,h*64+d] = P @ V
//  K6 outproj_kernel : out = attn @ Wo + bo
// ---------------------------------------------------------------------------

#define Bz   16
#define Nn   256
#define Dm   512
#define Hh   8
#define DK   64

__device__ float g_q   [Bz*Hh*Nn*DK];     // 2M
__device__ float g_k   [Bz*Hh*Nn*DK];     // 2M
__device__ float g_v   [Bz*Hh*Nn*DK];     // 2M
__device__ float g_bias[Bz*Hh*Nn*Nn];     // 8M  (bias -> logits -> probs)
__device__ float g_attn[Bz*Nn*Dm];        // 2M

// ---------------------------------------------------------------------------
// 128x128x8 register-tiled SGEMM body.  M=4096, N=512, K=512 fixed.
// 256 threads, 8x8 micro-tile per thread (2x2 blocks of 4x4).
// PERM=true stores C in the [B,H,N,64] attention layout.
// ---------------------------------------------------------------------------
template <bool PERM>
__device__ __forceinline__ void gemm_body(const float* __restrict__ A,
                                          const float* __restrict__ W,
                                          const float* __restrict__ bias,
                                          float* __restrict__ C)
{
    __shared__ float As[8][132];
    __shared__ float Bs[8][132];

    const int t  = threadIdx.x;
    const int tx = t & 15;
    const int ty = t >> 4;
    const int rowBase = blockIdx.y * 128;
    const int colBase = blockIdx.x * 128;

    const int arow = t >> 1;         // 0..127
    const int acol = (t & 1) * 4;    // 0 or 4
    const int brow = t >> 5;         // 0..7
    const int bcol = (t & 31) * 4;   // 0..124

    const float* Aptr = A + (rowBase + arow) * Dm + acol;
    const float* Wptr = W + brow * Dm + colBase + bcol;

    float acc[8][8];
#pragma unroll
    for (int i = 0; i < 8; ++i)
#pragma unroll
        for (int j = 0; j < 8; ++j) acc[i][j] = 0.0f;

    for (int k0 = 0; k0 < Dm; k0 += 8) {
        float4 av = *(const float4*)(Aptr + k0);
        float4 bv = *(const float4*)(Wptr + (size_t)k0 * Dm);
        As[acol + 0][arow] = av.x;
        As[acol + 1][arow] = av.y;
        As[acol + 2][arow] = av.z;
        As[acol + 3][arow] = av.w;
        *(float4*)&Bs[brow][bcol] = bv;
        __syncthreads();

#pragma unroll
        for (int kk = 0; kk < 8; ++kk) {
            float a[8], b[8];
            *(float4*)(&a[0]) = *(const float4*)(&As[kk][ty * 4]);
            *(float4*)(&a[4]) = *(const float4*)(&As[kk][64 + ty * 4]);
            *(float4*)(&b[0]) = *(const float4*)(&Bs[kk][tx * 4]);
            *(float4*)(&b[4]) = *(const float4*)(&Bs[kk][64 + tx * 4]);
#pragma unroll
            for (int i = 0; i < 8; ++i)
#pragma unroll
                for (int j = 0; j < 8; ++j)
                    acc[i][j] = fmaf(a[i], b[j], acc[i][j]);
        }
        __syncthreads();
    }

#pragma unroll
    for (int i = 0; i < 8; ++i) {
        int r = rowBase + ((i < 4) ? (ty * 4 + i) : (64 + ty * 4 + (i - 4)));
#pragma unroll
        for (int j = 0; j < 8; ++j) {
            int c = colBase + ((j < 4) ? (tx * 4 + j) : (64 + tx * 4 + (j - 4)));
            float v = acc[i][j] + bias[c];
            if (PERM) {
                int b_ = r >> 8, n_ = r & 255, h_ = c >> 6, d_ = c & 63;
                C[(((b_ * Hh + h_) * Nn) + n_) * DK + d_] = v;
            } else {
                C[r * Dm + c] = v;
            }
        }
    }
}

__global__ __launch_bounds__(256, 2)
void qkv_kernel(const float* __restrict__ xq, const float* __restrict__ xk,
                const float* __restrict__ xv,
                const float* __restrict__ Wq, const float* __restrict__ bq,
                const float* __restrict__ Wk, const float* __restrict__ bk,
                const float* __restrict__ Wv, const float* __restrict__ bv)
{
    const float* A; const float* W; const float* bias; float* C;
    if (blockIdx.z == 0)      { A = xq; W = Wq; bias = bq; C = g_q; }
    else if (blockIdx.z == 1) { A = xk; W = Wk; bias = bk; C = g_k; }
    else                      { A = xv; W = Wv; bias = bv; C = g_v; }
    gemm_body<true>(A, W, bias, C);
}

__global__ __launch_bounds__(256, 2)
void outproj_kernel(const float* __restrict__ Wo, const float* __restrict__ bo,
                    float* __restrict__ out)
{
    gemm_body<false>(g_attn, Wo, bo, out);
}

// ---------------------------------------------------------------------------
// K2: geometric bias.  One block per (b,n), one thread per m.
// ---------------------------------------------------------------------------
__global__ void geo_bias_kernel(const float* __restrict__ box,
                                const int*   __restrict__ mask,
                                const float* __restrict__ WGw,
                                const float* __restrict__ WGb)
{
    __shared__ float Ws[8][32];
    __shared__ float Wc[8][32];
    __shared__ float Wb[8];

    const int t = threadIdx.x;      // m
    const int n = blockIdx.x;
    const int b = blockIdx.y;

    for (int idx = t; idx < Hh * 64; idx += 256) {
        int h = idx >> 6, j = idx & 63;
        float w = WGw[idx];
        if (j < 32) Ws[h][j] = w; else Wc[h][j - 32] = w;
    }
    if (t < 8) Wb[t] = WGb[t];
    __syncthreads();

    float4 bn = *(const float4*)(box + (b * Nn + n) * 4);
    float4 bm = *(const float4*)(box + (b * Nn + t) * 4);
    // box = (x_min, y_min, x_max, y_max)
    float cx1 = (bn.x + bn.z) * 0.5f, cy1 = (bn.y + bn.w) * 0.5f;
    float w1  = bn.z - bn.x + 1.0f,   h1  = bn.w - bn.y + 1.0f;
    float cx2 = (bm.x + bm.z) * 0.5f, cy2 = (bm.y + bm.w) * 0.5f;
    float w2  = bm.z - bm.x + 1.0f,   h2  = bm.w - bm.y + 1.0f;

    float pos[4];
    pos[0] = logf(fmaxf(fabsf((cx1 - cx2) / w1), 0.001f));
    pos[1] = logf(fmaxf(fabsf((cy1 - cy2) / h1), 0.001f));
    pos[2] = logf(w1 / w2);
    pos[3] = logf(h1 / h2);

    // dim_mat = 1000^(-f/8), f = 0..7
    const float dimv[8] = {1.0f, 0.42169650342f, 0.17782794100f, 0.07498942093f,
                           0.03162277660f, 0.01333521432f, 0.00562341325f,
                           0.00237137371f};

    float acc[8];
#pragma unroll
    for (int h = 0; h < 8; ++h) acc[h] = Wb[h];

#pragma unroll
    for (int p = 0; p < 4; ++p) {
        float base = 100.0f * pos[p];
#pragma unroll
        for (int f = 0; f < 8; ++f) {
            float s, c;
            sincosf(base * dimv[f], &s, &c);
            int j = p * 8 + f;
#pragma unroll
            for (int h = 0; h < 8; ++h) {
                acc[h] = fmaf(s, Ws[h][j], acc[h]);
                acc[h] = fmaf(c, Wc[h][j], acc[h]);
            }
        }
    }

    float mterm = (mask[b * Nn + t] == 0) ? -1e9f : 0.0f;
#pragma unroll
    for (int h = 0; h < 8; ++h) {
        float val = logf(fmaxf(acc[h], 1e-6f)) + mterm;   // relu folded into max
        g_bias[(((b * Hh + h) * Nn) + n) * Nn + t] = val;
    }
}

// ---------------------------------------------------------------------------
// K3: logits = bias + (q k^T)/8.   64x64 tile per block, 4x4 micro-tile.
// ---------------------------------------------------------------------------
__global__ void scores_kernel()
{
    const int z = blockIdx.z;                 // b*8+h
    const float* Q  = g_q + z * (Nn * DK);
    const float* Kp = g_k + z * (Nn * DK);
    float* S = g_bias + (size_t)z * (Nn * Nn);

    __shared__ float Qs[16][68];
    __shared__ float Ks[16][68];

    const int t = threadIdx.x;
    const int tx = t & 15, ty = t >> 4;
    const int lr = t >> 2;          // 0..63
    const int lc = (t & 3) * 4;     // 0,4,8,12
    const int rowBase = blockIdx.y * 64;
    const int colBase = blockIdx.x * 64;

    float acc[4][4];
#pragma unroll
    for (int i = 0; i < 4; ++i)
#pragma unroll
        for (int j = 0; j < 4; ++j) acc[i][j] = 0.0f;

    for (int k0 = 0; k0 < DK; k0 += 16) {
        float4 qv = *(const float4*)(Q  + (rowBase + lr) * DK + k0 + lc);
        float4 kv = *(const float4*)(Kp + (colBase + lr) * DK + k0 + lc);
        Qs[lc + 0][lr] = qv.x; Qs[lc + 1][lr] = qv.y;
        Qs[lc + 2][lr] = qv.z; Qs[lc + 3][lr] = qv.w;
        Ks[lc + 0][lr] = kv.x; Ks[lc + 1][lr] = kv.y;
        Ks[lc + 2][lr] = kv.z; Ks[lc + 3][lr] = kv.w;
        __syncthreads();
#pragma unroll
        for (int kk = 0; kk < 16; ++kk) {
            float a[4], bb[4];
            *(float4*)a  = *(const float4*)&Qs[kk][ty * 4];
            *(float4*)bb = *(const float4*)&Ks[kk][tx * 4];
#pragma unroll
            for (int i = 0; i < 4; ++i)
#pragma unroll
                for (int j = 0; j < 4; ++j)
                    acc[i][j] = fmaf(a[i], bb[j], acc[i][j]);
        }
        __syncthreads();
    }

#pragma unroll
    for (int i = 0; i < 4; ++i)
#pragma unroll
        for (int j = 0; j < 4; ++j) {
            int idx = (rowBase + ty * 4 + i) * Nn + colBase + tx * 4 + j;
            S[idx] = fmaf(acc[i][j], 0.125f, S[idx]);
        }
}

// ---------------------------------------------------------------------------
// K4: softmax over last dim (256), one block per row, in place.
// ---------------------------------------------------------------------------
__global__ void softmax_kernel()
{
    float* p = g_bias + (size_t)blockIdx.x * Nn;
    const int t = threadIdx.x;
    const int lane = t & 31, w = t >> 5;
    __shared__ float red[8];

    float v = p[t];
    float m = v;
#pragma unroll
    for (int o = 16; o > 0; o >>= 1)
        m = fmaxf(m, __shfl_xor_sync(0xffffffffu, m, o));
    if (lane == 0) red[w] = m;
    __syncthreads();
    float mx = red[0];
#pragma unroll
    for (int i = 1; i < 8; ++i) mx = fmaxf(mx, red[i]);

    float e = __expf(v - mx);
    float s = e;
#pragma unroll
    for (int o = 16; o > 0; o >>= 1)
        s += __shfl_xor_sync(0xffffffffu, s, o);
    __syncthreads();
    if (lane == 0) red[w] = s;
    __syncthreads();
    float sum = 0.0f;
#pragma unroll
    for (int i = 0; i < 8; ++i) sum += red[i];

    p[t] = e / sum;
}

// ---------------------------------------------------------------------------
// K5: attn_out = P @ V, stored as [B, N, H*64].
// ---------------------------------------------------------------------------
__global__ void pv_kernel()
{
    const int z = blockIdx.z;       // b*8+h
    const int b = z >> 3, h = z & 7;
    const float* P = g_bias + (size_t)z * (Nn * Nn);
    const float* V = g_v + z * (Nn * DK);

    __shared__ float Ps[16][68];
    __shared__ float Vs[16][68];

    const int t = threadIdx.x;
    const int tx = t & 15, ty = t >> 4;
    const int pr = t >> 2, pc = (t & 3) * 4;     // P: 64 rows x 16 k
    const int vk = t >> 4, vc = (t & 15) * 4;    // V: 16 k x 64 cols
    const int rowBase = blockIdx.y * 64;

    float acc[4][4];
#pragma unroll
    for (int i = 0; i < 4; ++i)
#pragma unroll
        for (int j = 0; j < 4; ++j) acc[i][j] = 0.0f;

    for (int k0 = 0; k0 < Nn; k0 += 16) {
        float4 pv4 = *(const float4*)(P + (rowBase + pr) * Nn + k0 + pc);
        float4 vv4 = *(const float4*)(V + (k0 + vk) * DK + vc);
        Ps[pc + 0][pr] = pv4.x; Ps[pc + 1][pr] = pv4.y;
        Ps[pc + 2][pr] = pv4.z; Ps[pc + 3][pr] = pv4.w;
        *(float4*)&Vs[vk][vc] = vv4;
        __syncthreads();
#pragma unroll
        for (int kk = 0; kk < 16; ++kk) {
            float a[4], bb[4];
            *(float4*)a  = *(const float4*)&Ps[kk][ty * 4];
            *(float4*)bb = *(const float4*)&Vs[kk][tx * 4];
#pragma unroll
            for (int i = 0; i < 4; ++i)
#pragma unroll
                for (int j = 0; j < 4; ++j)
                    acc[i][j] = fmaf(a[i], bb[j], acc[i][j]);
        }
        __syncthreads();
    }

#pragma unroll
    for (int i = 0; i < 4; ++i) {
        int n = rowBase + ty * 4 + i;
#pragma unroll
        for (int j = 0; j < 4; ++j) {
            int d = tx * 4 + j;
            g_attn[(b * Nn + n) * Dm + h * DK + d] = acc[i][j];
        }
    }
}

// ---------------------------------------------------------------------------
extern "C" void kernel_launch(void* const* d_in, const int* in_sizes, int n_in,
                              void* d_out, int out_size)
{
    const float* xq  = (const float*)d_in[0];
    const float* xk  = (const float*)d_in[1];
    const float* xv  = (const float*)d_in[2];
    const float* box = (const float*)d_in[3];
    const int*   msk = (const int*)  d_in[4];
    const float* Wq  = (const float*)d_in[5];
    const float* bq  = (const float*)d_in[6];
    const float* Wk  = (const float*)d_in[7];
    const float* bk  = (const float*)d_in[8];
    const float* Wv  = (const float*)d_in[9];
    const float* bv  = (const float*)d_in[10];
    const float* Wo  = (const float*)d_in[11];
    const float* bo  = (const float*)d_in[12];
    const float* WGw = (const float*)d_in[13];
    const float* WGb = (const float*)d_in[14];
    float* out = (float*)d_out;

    qkv_kernel<<<dim3(4, 32, 3), 256>>>(xq, xk, xv, Wq, bq, Wk, bk, Wv, bv);
    geo_bias_kernel<<<dim3(Nn, Bz), 256>>>(box, msk, WGw, WGb);
    scores_kernel<<<dim3(4, 4, Bz * Hh), 256>>>();
    softmax_kernel<<<Bz * Hh * Nn, 256>>>();
    pv_kernel<<<dim3(1, 4, Bz * Hh), 256>>>();
    outproj_kernel<<<dim3(4, 32, 1), 256>>>(Wo, bo, out);
}

// round 3
// speedup vs baseline: 1.5644x; 1.5644x over previous
#include <cuda_runtime.h>
#include <cuda_bf16.h>
#include <cstdint>

// ---------------------------------------------------------------------------
// BoxMultiHeadedAttention  (B=16, N=256, D=512, H=8, d_k=64, dim_g=64)
//
//  K1 qkv_tf32       : q,k,v = (X @ W + b) -> [B,H,N,64]   (tf32 tensor-core)
//  K2 geo_bias_kernel: bias[b,h,n,m] = log(max(relu(geo.Wg+bg),1e-6)) (+mask)
//  K3 scores_softmax : probs = softmax(bias + qk^T/8)  (fused, in place)
//  K4 pv_kernel      : attn[b,n,h*64+d] = P @ V
//  K5 outproj_tf32   : out = attn @ Wo + bo             (tf32 tensor-core)
// ---------------------------------------------------------------------------

#define Bz   16
#define Nn   256
#define Dm   512
#define Hh   8
#define DK   64

__device__ float g_q   [Bz*Hh*Nn*DK];
__device__ float g_k   [Bz*Hh*Nn*DK];
__device__ float g_v   [Bz*Hh*Nn*DK];
__device__ float g_bias[Bz*Hh*Nn*Nn];     // bias -> probs (in place)
__device__ float g_attn[Bz*Nn*Dm];

__device__ __forceinline__ float to_tf32(float x) {
    uint32_t u;
    asm("cvt.rna.tf32.f32 %0, %1;" : "=r"(u) : "f"(x));
    return __uint_as_float(u);
}

__device__ __forceinline__ void mma_tf32(float c[4],
                                         uint32_t a0, uint32_t a1, uint32_t a2, uint32_t a3,
                                         uint32_t b0, uint32_t b1) {
    asm volatile(
        "mma.sync.aligned.m16n8k8.row.col.f32.tf32.tf32.f32 "
        "{%0,%1,%2,%3}, {%4,%5,%6,%7}, {%8,%9}, {%0,%1,%2,%3};\n"
        : "+f"(c[0]), "+f"(c[1]), "+f"(c[2]), "+f"(c[3])
        : "r"(a0), "r"(a1), "r"(a2), "r"(a3), "r"(b0), "r"(b1));
}

// ---------------------------------------------------------------------------
// tf32 tensor-core GEMM: C[M=rows,512] = A[.,512] @ W[512,512] + bias
// Block tile 128x128, 8 warps, warp tile 32x64, k-chunk 32.
// PERM=true stores C in the [B,H,N,64] attention layout.
// ---------------------------------------------------------------------------
template <bool PERM>
__device__ __forceinline__ void gemm_tf32_body(const float* __restrict__ A,
                                               const float* __restrict__ W,
                                               const float* __restrict__ bias,
                                               float* __restrict__ C)
{
    __shared__ float As[128][36];   // [m][k] padded: conflict-free frag reads
    __shared__ float Bs[32][136];   // [k][n] padded: conflict-free frag reads

    const int t    = threadIdx.x;
    const int lane = t & 31;
    const int w    = t >> 5;
    const int g    = lane >> 2;     // groupID
    const int tig  = lane & 3;      // threadID_in_group
    const int wm   = w >> 1;        // 0..3  (m warps)
    const int wn   = w & 1;         // 0..1  (n warps)
    const int rowBase = blockIdx.y * 128;
    const int colBase = blockIdx.x * 128;

    // A stage mapping: row = t>>1 (0..127), k-half = (t&1)*16
    const int ar = t >> 1, ak = (t & 1) * 16;
    const float* Ap = A + (size_t)(rowBase + ar) * Dm + ak;
    // B stage mapping: k = t>>3 (0..31), n-base = (t&7)*16
    const int bk = t >> 3, bn = (t & 7) * 16;
    const float* Wp = W + (size_t)bk * Dm + colBase + bn;

    float acc[2][8][4];
#pragma unroll
    for (int mt = 0; mt < 2; ++mt)
#pragma unroll
        for (int nt = 0; nt < 8; ++nt)
#pragma unroll
            for (int i = 0; i < 4; ++i) acc[mt][nt][i] = 0.0f;

    for (int k0 = 0; k0 < Dm; k0 += 32) {
#pragma unroll
        for (int i = 0; i < 4; ++i) {
            float4 v = *(const float4*)(Ap + k0 + i * 4);
            v.x = to_tf32(v.x); v.y = to_tf32(v.y);
            v.z = to_tf32(v.z); v.w = to_tf32(v.w);
            *(float4*)&As[ar][ak + i * 4] = v;
        }
#pragma unroll
        for (int i = 0; i < 4; ++i) {
            float4 v = *(const float4*)(Wp + (size_t)k0 * Dm + i * 4);
            v.x = to_tf32(v.x); v.y = to_tf32(v.y);
            v.z = to_tf32(v.z); v.w = to_tf32(v.w);
            *(float4*)&Bs[bk][bn + i * 4] = v;
        }
        __syncthreads();

#pragma unroll
        for (int ks = 0; ks < 32; ks += 8) {
            uint32_t afr[2][4];
#pragma unroll
            for (int mt = 0; mt < 2; ++mt) {
                int mr = wm * 32 + mt * 16 + g;
                afr[mt][0] = __float_as_uint(As[mr    ][ks + tig    ]);
                afr[mt][1] = __float_as_uint(As[mr + 8][ks + tig    ]);
                afr[mt][2] = __float_as_uint(As[mr    ][ks + tig + 4]);
                afr[mt][3] = __float_as_uint(As[mr + 8][ks + tig + 4]);
            }
            uint32_t bfr[8][2];
#pragma unroll
            for (int nt = 0; nt < 8; ++nt) {
                int nc = wn * 64 + nt * 8 + g;
                bfr[nt][0] = __float_as_uint(Bs[ks + tig    ][nc]);
                bfr[nt][1] = __float_as_uint(Bs[ks + tig + 4][nc]);
            }
#pragma unroll
            for (int mt = 0; mt < 2; ++mt)
#pragma unroll
                for (int nt = 0; nt < 8; ++nt)
                    mma_tf32(acc[mt][nt],
                             afr[mt][0], afr[mt][1], afr[mt][2], afr[mt][3],
                             bfr[nt][0], bfr[nt][1]);
        }
        __syncthreads();
    }

    // epilogue: c0:(g,2tig) c1:(g,2tig+1) c2:(g+8,2tig) c3:(g+8,2tig+1)
#pragma unroll
    for (int mt = 0; mt < 2; ++mt) {
#pragma unroll
        for (int nt = 0; nt < 8; ++nt) {
            int r0 = rowBase + wm * 32 + mt * 16 + g;
            int c0 = colBase + wn * 64 + nt * 8 + 2 * tig;
            float v00 = acc[mt][nt][0] + bias[c0];
            float v01 = acc[mt][nt][1] + bias[c0 + 1];
            float v10 = acc[mt][nt][2] + bias[c0];
            float v11 = acc[mt][nt][3] + bias[c0 + 1];
            if (PERM) {
                int b_ = r0 >> 8, n_ = r0 & 255, h_ = c0 >> 6, d_ = c0 & 63;
                float* p0 = C + ((((b_ * Hh + h_) * Nn) + n_) * DK + d_);
                p0[0] = v00; p0[1] = v01;
                int r1 = r0 + 8;
                int b1_ = r1 >> 8, n1_ = r1 & 255;
                float* p1 = C + ((((b1_ * Hh + h_) * Nn) + n1_) * DK + d_);
                p1[0] = v10; p1[1] = v11;
            } else {
                *(float2*)(C + (size_t)r0 * Dm + c0)       = make_float2(v00, v01);
                *(float2*)(C + (size_t)(r0 + 8) * Dm + c0) = make_float2(v10, v11);
            }
        }
    }
}

__global__ __launch_bounds__(256, 2)
void qkv_tf32(const float* __restrict__ xq, const float* __restrict__ xk,
              const float* __restrict__ xv,
              const float* __restrict__ Wq, const float* __restrict__ bq,
              const float* __restrict__ Wk, const float* __restrict__ bk,
              const float* __restrict__ Wv, const float* __restrict__ bv)
{
    const float* A; const float* W; const float* bias; float* C;
    if (blockIdx.z == 0)      { A = xq; W = Wq; bias = bq; C = g_q; }
    else if (blockIdx.z == 1) { A = xk; W = Wk; bias = bk; C = g_k; }
    else                      { A = xv; W = Wv; bias = bv; C = g_v; }
    gemm_tf32_body<true>(A, W, bias, C);
}

__global__ __launch_bounds__(256, 2)
void outproj_tf32(const float* __restrict__ Wo, const float* __restrict__ bo,
                  float* __restrict__ out)
{
    gemm_tf32_body<false>(g_attn, Wo, bo, out);
}

// ---------------------------------------------------------------------------
// K2: geometric bias.  One block per (b,n), one thread per m.
// ---------------------------------------------------------------------------
__global__ void geo_bias_kernel(const float* __restrict__ box,
                                const int*   __restrict__ mask,
                                const float* __restrict__ WGw,
                                const float* __restrict__ WGb)
{
    __shared__ float Ws[8][32];
    __shared__ float Wc[8][32];
    __shared__ float Wb[8];

    const int t = threadIdx.x;      // m
    const int n = blockIdx.x;
    const int b = blockIdx.y;

    for (int idx = t; idx < Hh * 64; idx += 256) {
        int h = idx >> 6, j = idx & 63;
        float w = WGw[idx];
        if (j < 32) Ws[h][j] = w; else Wc[h][j - 32] = w;
    }
    if (t < 8) Wb[t] = WGb[t];
    __syncthreads();

    float4 bn = *(const float4*)(box + (b * Nn + n) * 4);
    float4 bm = *(const float4*)(box + (b * Nn + t) * 4);
    float cx1 = (bn.x + bn.z) * 0.5f, cy1 = (bn.y + bn.w) * 0.5f;
    float w1  = bn.z - bn.x + 1.0f,   h1  = bn.w - bn.y + 1.0f;
    float cx2 = (bm.x + bm.z) * 0.5f, cy2 = (bm.y + bm.w) * 0.5f;
    float w2  = bm.z - bm.x + 1.0f,   h2  = bm.w - bm.y + 1.0f;

    float pos[4];
    pos[0] = logf(fmaxf(fabsf((cx1 - cx2) / w1), 0.001f));
    pos[1] = logf(fmaxf(fabsf((cy1 - cy2) / h1), 0.001f));
    pos[2] = logf(w1 / w2);
    pos[3] = logf(h1 / h2);

    const float dimv[8] = {1.0f, 0.42169650342f, 0.17782794100f, 0.07498942093f,
                           0.03162277660f, 0.01333521432f, 0.00562341325f,
                           0.00237137371f};

    float acc[8];
#pragma unroll
    for (int h = 0; h < 8; ++h) acc[h] = Wb[h];

#pragma unroll
    for (int p = 0; p < 4; ++p) {
        float base = 100.0f * pos[p];
#pragma unroll
        for (int f = 0; f < 8; ++f) {
            float s, c;
            sincosf(base * dimv[f], &s, &c);
            int j = p * 8 + f;
#pragma unroll
            for (int h = 0; h < 8; ++h) {
                acc[h] = fmaf(s, Ws[h][j], acc[h]);
                acc[h] = fmaf(c, Wc[h][j], acc[h]);
            }
        }
    }

    float mterm = (mask[b * Nn + t] == 0) ? -1e9f : 0.0f;
#pragma unroll
    for (int h = 0; h < 8; ++h) {
        float val = logf(fmaxf(acc[h], 1e-6f)) + mterm;
        g_bias[(((b * Hh + h) * Nn) + n) * Nn + t] = val;
    }
}

// ---------------------------------------------------------------------------
// K3: fused scores + softmax.  Block = 64 query rows x all 256 keys for one
// (b,h).  probs written back in place over g_bias.
// ---------------------------------------------------------------------------
__global__ __launch_bounds__(256)
void scores_softmax_kernel()
{
    const int z = blockIdx.y;                 // b*8+h
    const float* Q  = g_q + (size_t)z * (Nn * DK);
    const float* Km = g_k + (size_t)z * (Nn * DK);
    float* S = g_bias + (size_t)z * (Nn * Nn);
    const int rowBase = blockIdx.x * 64;

    __shared__ float Qs[16][68];
    __shared__ float Ks[16][260];

    const int t  = threadIdx.x;
    const int tx = t & 15;       // 16 col groups
    const int ty = t >> 4;       // 16 row groups (4 rows each)

    float acc[4][16];
#pragma unroll
    for (int i = 0; i < 4; ++i)
#pragma unroll
        for (int j = 0; j < 16; ++j) acc[i][j] = 0.0f;

    const int qr = t >> 2, qc = (t & 3) * 4;

    for (int d0 = 0; d0 < DK; d0 += 16) {
        float4 qv = *(const float4*)(Q + (rowBase + qr) * DK + d0 + qc);
        Qs[qc + 0][qr] = qv.x; Qs[qc + 1][qr] = qv.y;
        Qs[qc + 2][qr] = qv.z; Qs[qc + 3][qr] = qv.w;
#pragma unroll
        for (int i = 0; i < 4; ++i) {
            float4 kv = *(const float4*)(Km + t * DK + d0 + i * 4);
            Ks[i * 4 + 0][t] = kv.x; Ks[i * 4 + 1][t] = kv.y;
            Ks[i * 4 + 2][t] = kv.z; Ks[i * 4 + 3][t] = kv.w;
        }
        __syncthreads();
#pragma unroll
        for (int kk = 0; kk < 16; ++kk) {
            float a[4], bvals[16];
            *(float4*)a = *(const float4*)&Qs[kk][ty * 4];
#pragma unroll
            for (int gI = 0; gI < 4; ++gI)
                *(float4*)&bvals[gI * 4] = *(const float4*)&Ks[kk][gI * 64 + tx * 4];
#pragma unroll
            for (int i = 0; i < 4; ++i)
#pragma unroll
                for (int j = 0; j < 16; ++j)
                    acc[i][j] = fmaf(a[i], bvals[j], acc[i][j]);
        }
        __syncthreads();
    }

    // scale + bias, then softmax per row (16 lanes per row: same ty)
    float mx[4] = {-1e30f, -1e30f, -1e30f, -1e30f};
#pragma unroll
    for (int i = 0; i < 4; ++i) {
        int row = rowBase + ty * 4 + i;
#pragma unroll
        for (int gI = 0; gI < 4; ++gI) {
            float4 bv = *(const float4*)(S + (size_t)row * Nn + gI * 64 + tx * 4);
            acc[i][gI * 4 + 0] = fmaf(acc[i][gI * 4 + 0], 0.125f, bv.x);
            acc[i][gI * 4 + 1] = fmaf(acc[i][gI * 4 + 1], 0.125f, bv.y);
            acc[i][gI * 4 + 2] = fmaf(acc[i][gI * 4 + 2], 0.125f, bv.z);
            acc[i][gI * 4 + 3] = fmaf(acc[i][gI * 4 + 3], 0.125f, bv.w);
        }
#pragma unroll
        for (int j = 0; j < 16; ++j) mx[i] = fmaxf(mx[i], acc[i][j]);
    }
#pragma unroll
    for (int off = 8; off > 0; off >>= 1)
#pragma unroll
        for (int i = 0; i < 4; ++i)
            mx[i] = fmaxf(mx[i], __shfl_xor_sync(0xffffffffu, mx[i], off));

    float sm[4] = {0.0f, 0.0f, 0.0f, 0.0f};
#pragma unroll
    for (int i = 0; i < 4; ++i)
#pragma unroll
        for (int j = 0; j < 16; ++j) {
            acc[i][j] = __expf(acc[i][j] - mx[i]);
            sm[i] += acc[i][j];
        }
#pragma unroll
    for (int off = 8; off > 0; off >>= 1)
#pragma unroll
        for (int i = 0; i < 4; ++i)
            sm[i] += __shfl_xor_sync(0xffffffffu, sm[i], off);

#pragma unroll
    for (int i = 0; i < 4; ++i) {
        float inv = __frcp_rn(sm[i]);
        int row = rowBase + ty * 4 + i;
#pragma unroll
        for (int gI = 0; gI < 4; ++gI) {
            float4 o;
            o.x = acc[i][gI * 4 + 0] * inv;
            o.y = acc[i][gI * 4 + 1] * inv;
            o.z = acc[i][gI * 4 + 2] * inv;
            o.w = acc[i][gI * 4 + 3] * inv;
            *(float4*)(S + (size_t)row * Nn + gI * 64 + tx * 4) = o;
        }
    }
}

// ---------------------------------------------------------------------------
// K4: attn_out = P @ V, stored as [B, N, H*64].
// ---------------------------------------------------------------------------
__global__ void pv_kernel()
{
    const int z = blockIdx.z;       // b*8+h
    const int b = z >> 3, h = z & 7;
    const float* P = g_bias + (size_t)z * (Nn * Nn);
    const float* V = g_v + (size_t)z * (Nn * DK);

    __shared__ float Ps[16][68];
    __shared__ float Vs[16][68];

    const int t = threadIdx.x;
    const int tx = t & 15, ty = t >> 4;
    const int pr = t >> 2, pc = (t & 3) * 4;
    const int vk = t >> 4, vc = (t & 15) * 4;
    const int rowBase = blockIdx.y * 64;

    float acc[4][4];
#pragma unroll
    for (int i = 0; i < 4; ++i)
#pragma unroll
        for (int j = 0; j < 4; ++j) acc[i][j] = 0.0f;

    for (int k0 = 0; k0 < Nn; k0 += 16) {
        float4 pv4 = *(const float4*)(P + (rowBase + pr) * Nn + k0 + pc);
        float4 vv4 = *(const float4*)(V + (k0 + vk) * DK + vc);
        Ps[pc + 0][pr] = pv4.x; Ps[pc + 1][pr] = pv4.y;
        Ps[pc + 2][pr] = pv4.z; Ps[pc + 3][pr] = pv4.w;
        *(float4*)&Vs[vk][vc] = vv4;
        __syncthreads();
#pragma unroll
        for (int kk = 0; kk < 16; ++kk) {
            float a[4], bb[4];
            *(float4*)a  = *(const float4*)&Ps[kk][ty * 4];
            *(float4*)bb = *(const float4*)&Vs[kk][tx * 4];
#pragma unroll
            for (int i = 0; i < 4; ++i)
#pragma unroll
                for (int j = 0; j < 4; ++j)
                    acc[i][j] = fmaf(a[i], bb[j], acc[i][j]);
        }
        __syncthreads();
    }

#pragma unroll
    for (int i = 0; i < 4; ++i) {
        int n = rowBase + ty * 4 + i;
#pragma unroll
        for (int j = 0; j < 4; ++j) {
            int d = tx * 4 + j;
            g_attn[(b * Nn + n) * Dm + h * DK + d] = acc[i][j];
        }
    }
}

// ---------------------------------------------------------------------------
extern "C" void kernel_launch(void* const* d_in, const int* in_sizes, int n_in,
                              void* d_out, int out_size)
{
    const float* xq  = (const float*)d_in[0];
    const float* xk  = (const float*)d_in[1];
    const float* xv  = (const float*)d_in[2];
    const float* box = (const float*)d_in[3];
    const int*   msk = (const int*)  d_in[4];
    const float* Wq  = (const float*)d_in[5];
    const float* bq  = (const float*)d_in[6];
    const float* Wk  = (const float*)d_in[7];
    const float* bk  = (const float*)d_in[8];
    const float* Wv  = (const float*)d_in[9];
    const float* bv  = (const float*)d_in[10];
    const float* Wo  = (const float*)d_in[11];
    const float* bo  = (const float*)d_in[12];
    const float* WGw = (const float*)d_in[13];
    const float* WGb = (const float*)d_in[14];
    float* out = (float*)d_out;

    qkv_tf32<<<dim3(4, 32, 3), 256>>>(xq, xk, xv, Wq, bq, Wk, bk, Wv, bv);
    geo_bias_kernel<<<dim3(Nn, Bz), 256>>>(box, msk, WGw, WGb);
    scores_softmax_kernel<<<dim3(4, Bz * Hh), 256>>>();
    pv_kernel<<<dim3(1, 4, Bz * Hh), 256>>>();
    outproj_tf32<<<dim3(4, 32, 1), 256>>>(Wo, bo, out);
}